// round 3
// baseline (speedup 1.0000x reference)
#include <cuda_runtime.h>
#include <cuda_bf16.h>
#include <math.h>

// Problem constants (from reference): N=100000, E=1600000, D=OUT=128.
// Sizes are read at runtime from in_sizes but scratch is statically sized.
#define MAX_N 100000
#define D_DIM 128
#define PAD_N (((MAX_N + 127) / 128) * 128)   // 100096, padded for GEMM tiles

// Scratch (device globals: allocation-free, zero-initialized at load).
__device__ float g_score[MAX_N];          // feature @ w_gate          [N]
__device__ int   g_seg[MAX_N + 1];        // segment starts in dst     [N+1]
__device__ float g_A[(size_t)PAD_N * D_DIM]; // normalized aggregated rows

// ---------------------------------------------------------------------------
// K1: per-node gate score (warp per node) + segment boundaries (binary search)
// ---------------------------------------------------------------------------
__device__ __forceinline__ int lower_bound_dev(const int* __restrict__ a, int n, int key) {
    int lo = 0, hi = n;
    while (lo < hi) {
        int mid = (lo + hi) >> 1;
        if (a[mid] < key) lo = mid + 1; else hi = mid;
    }
    return lo;
}

__global__ __launch_bounds__(256) void k1_score_seg(
    const float* __restrict__ feature,
    const int*   __restrict__ dst,
    const float* __restrict__ w_gate,
    int N, int E)
{
    // Part A: gate score, one warp per node (coalesced 512B row read)
    int n = blockIdx.x * 8 + (threadIdx.x >> 5);
    int lane = threadIdx.x & 31;
    if (n < N) {
        float4 f = ((const float4*)(feature + (size_t)n * D_DIM))[lane];
        float4 g = ((const float4*)w_gate)[lane];
        float p = f.x * g.x + f.y * g.y + f.z * g.z + f.w * g.w;
        #pragma unroll
        for (int o = 16; o; o >>= 1) p += __shfl_xor_sync(0xFFFFFFFFu, p, o);
        if (lane == 0) g_score[n] = p;
    }
    // Part B: segment starts, thread per index (dst is sorted)
    int gt = blockIdx.x * 256 + threadIdx.x;
    if (gt <= N) g_seg[gt] = lower_bound_dev(dst, E, gt);
}

// ---------------------------------------------------------------------------
// K2: per-node (warp) segment softmax + weighted feature aggregation.
//     A[n] = (sum_e exp(score[src_e]-m) * feature[src_e]) / (sum_e exp(...))
//     No atomics: each warp owns one contiguous dst segment.
// ---------------------------------------------------------------------------
__global__ __launch_bounds__(256) void k2_aggregate(
    const float* __restrict__ feature,
    const int*   __restrict__ src,
    int N)
{
    int warp = (blockIdx.x * blockDim.x + threadIdx.x) >> 5;
    int lane = threadIdx.x & 31;
    if (warp >= N) return;

    int s = g_seg[warp];
    int t = g_seg[warp + 1];
    float4* Arow = (float4*)(g_A + (size_t)warp * D_DIM);

    if (s == t) {  // empty segment -> zero row (matches reference: segment_sum of nothing)
        Arow[lane] = make_float4(0.f, 0.f, 0.f, 0.f);
        return;
    }

    // Pass 1: segment max of gate scores
    float m = -INFINITY;
    for (int base = s; base < t; base += 32) {
        int e = base + lane;
        float sc = (e < t) ? g_score[src[e]] : -INFINITY;
        m = fmaxf(m, sc);
    }
    #pragma unroll
    for (int o = 16; o; o >>= 1) m = fmaxf(m, __shfl_xor_sync(0xFFFFFFFFu, m, o));

    // Pass 2: weights + weighted accumulation of source feature rows.
    // Lane l accumulates feature dims [4l, 4l+4).
    float4 acc = make_float4(0.f, 0.f, 0.f, 0.f);
    float dsum = 0.f;
    for (int base = s; base < t; base += 32) {
        int e = base + lane;
        int sv = (e < t) ? src[e] : 0;
        float w = (e < t) ? expf(g_score[sv] - m) : 0.f;
        dsum += w;
        int cnt = min(32, t - base);
        #pragma unroll 4
        for (int j = 0; j < cnt; ++j) {
            float wj = __shfl_sync(0xFFFFFFFFu, w, j);
            int   sj = __shfl_sync(0xFFFFFFFFu, sv, j);
            float4 f = ((const float4*)(feature + (size_t)sj * D_DIM))[lane];
            acc.x = fmaf(wj, f.x, acc.x);
            acc.y = fmaf(wj, f.y, acc.y);
            acc.z = fmaf(wj, f.z, acc.z);
            acc.w = fmaf(wj, f.w, acc.w);
        }
    }
    #pragma unroll
    for (int o = 16; o; o >>= 1) dsum += __shfl_xor_sync(0xFFFFFFFFu, dsum, o);

    float inv = 1.f / dsum;   // dsum >= exp(0) = 1 since segment non-empty
    acc.x *= inv; acc.y *= inv; acc.z *= inv; acc.w *= inv;
    Arow[lane] = acc;
}

// ---------------------------------------------------------------------------
// K3: out[N,128] = A[N,128] @ W[128,128], fp32 tiled SGEMM.
//     BM=128, BN=128 (full), BK=16, 256 threads, 8x8 register tile.
// ---------------------------------------------------------------------------
#define BM 128
#define BK 16

__global__ __launch_bounds__(256) void k3_gemm(
    const float* __restrict__ A,
    const float* __restrict__ W,
    float* __restrict__ out,
    int N)
{
    __shared__ float As[BK][BM + 4];   // transposed A tile, padded
    __shared__ float Ws[BK][128];

    int tid = threadIdx.x;
    int tr = tid >> 4;       // 0..15
    int tc = tid & 15;       // 0..15
    int row0 = blockIdx.x * BM;

    float acc[8][8];
    #pragma unroll
    for (int i = 0; i < 8; ++i)
        #pragma unroll
        for (int j = 0; j < 8; ++j) acc[i][j] = 0.f;

    for (int k0 = 0; k0 < 128; k0 += BK) {
        // Load A tile (128 x 16) transposed into As[k][m]. 512 float4 loads.
        #pragma unroll
        for (int q = tid; q < (BM * BK) / 4; q += 256) {
            int r  = q >> 2;           // 0..127
            int kk = (q & 3) << 2;     // 0,4,8,12
            float4 v = *(const float4*)(A + (size_t)(row0 + r) * 128 + k0 + kk);
            As[kk + 0][r] = v.x;
            As[kk + 1][r] = v.y;
            As[kk + 2][r] = v.z;
            As[kk + 3][r] = v.w;
        }
        // Load W tile (16 x 128) directly.
        #pragma unroll
        for (int q = tid; q < (BK * 128) / 4; q += 256) {
            int r = q >> 5;            // 0..15
            int c = (q & 31) << 2;
            *(float4*)&Ws[r][c] = *(const float4*)(W + (size_t)(k0 + r) * 128 + c);
        }
        __syncthreads();

        #pragma unroll
        for (int k = 0; k < BK; ++k) {
            float a[8], w[8];
            *(float4*)(a)     = *(float4*)&As[k][tr * 8];
            *(float4*)(a + 4) = *(float4*)&As[k][tr * 8 + 4];
            *(float4*)(w)     = *(float4*)&Ws[k][tc * 8];
            *(float4*)(w + 4) = *(float4*)&Ws[k][tc * 8 + 4];
            #pragma unroll
            for (int i = 0; i < 8; ++i)
                #pragma unroll
                for (int j = 0; j < 8; ++j)
                    acc[i][j] = fmaf(a[i], w[j], acc[i][j]);
        }
        __syncthreads();
    }

    #pragma unroll
    for (int i = 0; i < 8; ++i) {
        int row = row0 + tr * 8 + i;
        if (row < N) {
            float* o = out + (size_t)row * 128 + tc * 8;
            *(float4*)(o)     = make_float4(acc[i][0], acc[i][1], acc[i][2], acc[i][3]);
            *(float4*)(o + 4) = make_float4(acc[i][4], acc[i][5], acc[i][6], acc[i][7]);
        }
    }
}

// ---------------------------------------------------------------------------
// Launch
// ---------------------------------------------------------------------------
extern "C" void kernel_launch(void* const* d_in, const int* in_sizes, int n_in,
                              void* d_out, int out_size)
{
    const float* feature = (const float*)d_in[0];  // [N,128]
    const int*   src     = (const int*)  d_in[1];  // [E]
    const int*   dst     = (const int*)  d_in[2];  // [E], sorted
    const float* w_gate  = (const float*)d_in[3];  // [128,1]
    const float* w_feat  = (const float*)d_in[4];  // [128,128]
    float*       out     = (float*)d_out;          // [N,128]

    int N = in_sizes[0] / D_DIM;
    int E = in_sizes[1];

    float* g_A_ptr = nullptr;
    cudaGetSymbolAddress((void**)&g_A_ptr, g_A);

    // K1: gate scores (warp/node) + segment starts (thread/index)
    k1_score_seg<<<(N + 7) / 8, 256>>>(feature, dst, w_gate, N, E);

    // K2: one warp per node, segment softmax + weighted aggregation
    int warps_needed = N;
    int blocks2 = (warps_needed * 32 + 255) / 256;
    k2_aggregate<<<blocks2, 256>>>(feature, src, N);

    // K3: out = A @ w_feat
    int blocks3 = (N + BM - 1) / BM;
    k3_gemm<<<blocks3, 256>>>(g_A_ptr, w_feat, out, N);
}